// round 14
// baseline (speedup 1.0000x reference)
#include <cuda_runtime.h>
#include <cuda_fp16.h>
#include <math.h>
#include <stdint.h>

// Problem dims (fixed)
#define BB   64
#define TT   20
#define FF   2048
#define EE   512
#define GG   1024
#define VV   32000
#define MROWS (BB*TT)   // 1280

// Scratch (device globals; no allocation allowed)
__device__ float  d_GI [MROWS * 3 * GG];
__device__ float  d_HS [MROWS * GG];
__device__ __half d_HSh[MROWS * GG];
__device__ __half d_Xh [MROWS * EE];
__device__ __half d_feat_h[BB * FF];
__device__ __half d_Wih_h [3 * GG * EE];
__device__ __half d_Whh_h [3 * GG * GG];
__device__ __half d_imgv_h[EE * FF];
__device__ __half d_fcv_h [VV * GG];
__device__ unsigned d_gru_bar;            // global step barrier (reset in prep)

// ---------------------------------------------------------------- helpers
__device__ __forceinline__ void mma_f16(float c[4], const unsigned a[4], const unsigned b[2]) {
    asm volatile(
      "mma.sync.aligned.m16n8k16.row.col.f32.f16.f16.f32 "
      "{%0,%1,%2,%3},{%4,%5,%6,%7},{%8,%9},{%0,%1,%2,%3};\n"
      : "+f"(c[0]), "+f"(c[1]), "+f"(c[2]), "+f"(c[3])
      : "r"(a[0]), "r"(a[1]), "r"(a[2]), "r"(a[3]), "r"(b[0]), "r"(b[1]));
}
__device__ __forceinline__ void ldm_x4(unsigned& r0, unsigned& r1, unsigned& r2, unsigned& r3,
                                       const __half* p) {
    unsigned a = (unsigned)__cvta_generic_to_shared(p);
    asm volatile("ldmatrix.sync.aligned.m8n8.x4.shared.b16 {%0,%1,%2,%3}, [%4];"
                 : "=r"(r0), "=r"(r1), "=r"(r2), "=r"(r3) : "r"(a));
}
__device__ __forceinline__ void cp16(unsigned dst, const void* src) {
    asm volatile("cp.async.cg.shared.global [%0], [%1], 16;\n" :: "r"(dst), "l"(src));
}
__device__ __forceinline__ void cp_commit() {
    asm volatile("cp.async.commit_group;\n" ::: "memory");
}
template<int N> __device__ __forceinline__ void cp_wait() {
    asm volatile("cp.async.wait_group %0;\n" :: "n"(N) : "memory");
}
__device__ __forceinline__ float sigmoidf_fast(float x) {
    return 1.0f / (1.0f + __expf(-x));
}
__device__ __forceinline__ int swz(int row, int k) {
    int c = k >> 3;
    return ((row >> 1) << 6) + ((((((row & 1) << 2) | c)) ^ ((row >> 1) & 7)) << 3) + (k & 7);
}

// ---------------------------------------------------------------- merged prep (main stream)
//   [0, 128)      : f2h features
//   [128, 1664)   : f2h W_ih
//   [1664, 1728)  : weight-norm img_v rows (warp per row, K=2048)
//   [1728, 2336)  : embedding gather (2 rows/block)
// (W_hh f2h moved to the side stream — only the GRU needs it)
#define PREP_BLOCKS 2336

__global__ __launch_bounds__(256) void prep_kernel(
    const float* __restrict__ features,
    const float* __restrict__ W_ih,
    const float* __restrict__ img_v, const float* __restrict__ img_g,
    const int*   __restrict__ ids,   const float* __restrict__ emb,
    __half* __restrict__ feat_h, __half* __restrict__ Wih_h,
    __half* __restrict__ imgv_h) {
    const int bid = blockIdx.x, tid = threadIdx.x;
    if (bid == 0 && tid == 0) d_gru_bar = 0;

    if (bid < 1664) {
        const float* src; __half* dst; int base;
        if (bid < 128) { src = features; dst = feat_h; base = bid; }
        else           { src = W_ih;     dst = Wih_h;  base = bid - 128; }
        int i = (base * 256 + tid) * 4;
        float4 v = *(const float4*)(src + i);
        __half2* d = (__half2*)(dst + i);
        d[0] = __floats2half2_rn(v.x, v.y);
        d[1] = __floats2half2_rn(v.z, v.w);
    } else if (bid < 1728) {
        int w = (bid - 1664) * 8 + (tid >> 5);   // row 0..511
        int lane = tid & 31;
        const float4* v = (const float4*)(img_v + (size_t)w * FF);
        float s = 0.f;
        #pragma unroll
        for (int i = 0; i < 16; ++i) {
            float4 x = v[i * 32 + lane];
            s += x.x*x.x + x.y*x.y + x.z*x.z + x.w*x.w;
        }
        #pragma unroll
        for (int o = 16; o; o >>= 1) s += __shfl_xor_sync(0xffffffffu, s, o);
        float sc = img_g[w] / sqrtf(s);
        uint2* o2 = (uint2*)(imgv_h + (size_t)w * FF);
        #pragma unroll
        for (int i = 0; i < 16; ++i) {
            float4 x = v[i * 32 + lane];
            __half2 a = __floats2half2_rn(x.x * sc, x.y * sc);
            __half2 b = __floats2half2_rn(x.z * sc, x.w * sc);
            uint2 pk; pk.x = *(unsigned*)&a; pk.y = *(unsigned*)&b;
            o2[i * 32 + lane] = pk;
        }
    } else {
        int r = (bid - 1728) * 2 + (tid >> 7);   // 0..1215
        int t = r / BB + 1, b = r % BB;
        int id = ids[b * TT + t];
        int i = tid & 127;
        const float4* src = (const float4*)(emb + (size_t)id * EE);
        __half2* dst = (__half2*)(d_Xh + ((size_t)t * BB + b) * EE);
        float4 v = src[i];
        dst[2*i]   = __floats2half2_rn(v.x, v.y);
        dst[2*i+1] = __floats2half2_rn(v.z, v.w);
    }
}

// plain f2h (side stream: W_hh)
__global__ void f2h_kernel(const float* __restrict__ src, __half* __restrict__ dst, int n) {
    int i = (blockIdx.x * blockDim.x + threadIdx.x) * 4;
    if (i < n) {
        float4 v = *(const float4*)(src + i);
        __half2* d = (__half2*)(dst + i);
        d[0] = __floats2half2_rn(v.x, v.y);
        d[1] = __floats2half2_rn(v.z, v.w);
    }
}

// weight-norm fold + convert, K=1024 (fc_v), warp per row, register-resident
__global__ __launch_bounds__(256) void wn1024_kernel(
    const float* __restrict__ V, const float* __restrict__ g, __half* __restrict__ out,
    int rows) {
    int w = (blockIdx.x * blockDim.x + threadIdx.x) >> 5;
    if (w >= rows) return;
    int lane = threadIdx.x & 31;
    const float4* v = (const float4*)(V + (size_t)w * 1024);
    float4 buf[8];
    float s = 0.f;
    #pragma unroll
    for (int i = 0; i < 8; ++i) {
        buf[i] = v[i * 32 + lane];
        s += buf[i].x*buf[i].x + buf[i].y*buf[i].y + buf[i].z*buf[i].z + buf[i].w*buf[i].w;
    }
    #pragma unroll
    for (int o = 16; o; o >>= 1) s += __shfl_xor_sync(0xffffffffu, s, o);
    float sc = g[w] / sqrtf(s);
    uint2* o2 = (uint2*)(out + (size_t)w * 1024);
    #pragma unroll
    for (int i = 0; i < 8; ++i) {
        __half2 a = __floats2half2_rn(buf[i].x * sc, buf[i].y * sc);
        __half2 b = __floats2half2_rn(buf[i].z * sc, buf[i].w * sc);
        uint2 pk; pk.x = *(unsigned*)&a; pk.y = *(unsigned*)&b;
        o2[i * 32 + lane] = pk;
    }
}

// ---------------------------------------------------------------- mma.sync GEMM v1 (img only)
template<int REMAP, int OUTHALF>
__global__ __launch_bounds__(256) void gemm_f16_kernel(
    const __half* __restrict__ A, const __half* __restrict__ B, void* __restrict__ Cv,
    const float* __restrict__ bias, int Mreal, int N, int K) {
    __shared__ __half sA[2][128 * 32];
    __shared__ __half sB[2][128 * 32];

    const int tid = threadIdx.x, lane = tid & 31, warp = tid >> 5;
    const int wm = warp >> 2, wn = warp & 3;
    const int m0 = blockIdx.x * 128, n0 = blockIdx.y * 128;

    float acc[4][4][4];
    #pragma unroll
    for (int i = 0; i < 4; ++i)
        #pragma unroll
        for (int j = 0; j < 4; ++j)
            #pragma unroll
            for (int k = 0; k < 4; ++k) acc[i][j][k] = 0.f;

    const int nk = K >> 5;

    auto stage = [&](int kt, int buf) {
        int kofs = kt * 32;
        #pragma unroll
        for (int j = 0; j < 2; ++j) {
            int idx = tid + j * 256;
            int row = idx >> 2, ch = (idx & 3) * 8;
            int arow = m0 + row; if (arow >= Mreal) arow = Mreal - 1;
            cp16((unsigned)__cvta_generic_to_shared(&sA[buf][swz(row, ch)]),
                 A + (size_t)arow * K + kofs + ch);
            cp16((unsigned)__cvta_generic_to_shared(&sB[buf][swz(row, ch)]),
                 B + (size_t)(n0 + row) * K + kofs + ch);
        }
    };

    stage(0, 0); cp_commit();

    for (int kt = 0; kt < nk; ++kt) {
        __syncthreads();
        if (kt + 1 < nk) { stage(kt + 1, (kt + 1) & 1); cp_commit(); cp_wait<1>(); }
        else             { cp_wait<0>(); }
        __syncthreads();
        const int buf = kt & 1;
        #pragma unroll
        for (int ks = 0; ks < 32; ks += 16) {
            unsigned af[4][4];
            #pragma unroll
            for (int mf = 0; mf < 4; ++mf) {
                int row = wm * 64 + mf * 16 + (lane & 15);
                ldm_x4(af[mf][0], af[mf][1], af[mf][2], af[mf][3],
                       &sA[buf][swz(row, ks + ((lane >> 4) << 3))]);
            }
            unsigned bf[4][2];
            #pragma unroll
            for (int nf2 = 0; nf2 < 2; ++nf2) {
                int g = lane >> 3;
                int row = wn * 32 + nf2 * 16 + ((g >> 1) << 3) + (lane & 7);
                unsigned t0, t1, t2, t3;
                ldm_x4(t0, t1, t2, t3, &sB[buf][swz(row, ks + ((g & 1) << 3))]);
                bf[nf2*2][0] = t0; bf[nf2*2][1] = t1;
                bf[nf2*2+1][0] = t2; bf[nf2*2+1][1] = t3;
            }
            #pragma unroll
            for (int mf = 0; mf < 4; ++mf)
                #pragma unroll
                for (int nf = 0; nf < 4; ++nf)
                    mma_f16(acc[mf][nf], af[mf], bf[nf]);
        }
    }

    #pragma unroll
    for (int mf = 0; mf < 4; ++mf) {
        #pragma unroll
        for (int nf = 0; nf < 4; ++nf) {
            int row = m0 + wm * 64 + mf * 16 + (lane >> 2);
            int col = n0 + wn * 32 + nf * 8 + (lane & 3) * 2;
            float b0 = bias ? bias[col]     : 0.f;
            float b1 = bias ? bias[col + 1] : 0.f;
            #pragma unroll
            for (int half = 0; half < 2; ++half) {
                int r = row + half * 8;
                if (r >= Mreal) continue;
                float v0 = acc[mf][nf][half*2 + 0] + b0;
                float v1 = acc[mf][nf][half*2 + 1] + b1;
                size_t idx;
                if (REMAP) { int b_ = r & 63, t_ = r >> 6; idx = ((size_t)(b_ * TT + t_)) * N + col; }
                else       { idx = (size_t)r * N + col; }
                if (OUTHALF) *(__half2*)((__half*)Cv + idx) = __floats2half2_rn(v0, v1);
                else         *(float2*)((float*)Cv + idx)   = make_float2(v0, v1);
            }
        }
    }
}

// ---------------------------------------------------------------- mma.sync GEMM v3 (FC, GI)
// 256 threads (8 warps 2x4), BM=BN=128, BK=32, 4-stage cp.async ring,
// stage-before-barrier, ONE __syncthreads per k-tile, depth-2 prefetch, 2 CTAs/SM.
#define V3_TILE 4096
#define V3_SMEM (8 * V3_TILE * 2)          // 64 KB

template<int REMAP>
__global__ __launch_bounds__(256, 2) void gemm_f16_v3(
    const __half* __restrict__ A, const __half* __restrict__ B, float* __restrict__ C,
    const float* __restrict__ bias, int Mreal, int N, int K, int m_ofs) {
    extern __shared__ __half sh[];
    __half* shB = sh + 4 * V3_TILE;

    const int tid = threadIdx.x, lane = tid & 31, warp = tid >> 5;
    const int wm = warp >> 2, wn = warp & 3;
    const int m0 = m_ofs + blockIdx.x * 128, n0 = blockIdx.y * 128;

    float acc[4][4][4];
    #pragma unroll
    for (int i = 0; i < 4; ++i)
        #pragma unroll
        for (int j = 0; j < 4; ++j)
            #pragma unroll
            for (int k = 0; k < 4; ++k) acc[i][j][k] = 0.f;

    const int nk = K >> 5;

    const int s_row = tid >> 2, s_c = (tid & 3) * 8;
    int ar0 = m0 + s_row;      if (ar0 >= Mreal) ar0 = Mreal - 1;
    int ar1 = m0 + s_row + 64; if (ar1 >= Mreal) ar1 = Mreal - 1;
    const __half* gA0 = A + (size_t)ar0 * K + s_c;
    const __half* gA1 = A + (size_t)ar1 * K + s_c;
    const __half* gB0 = B + (size_t)(n0 + s_row)      * K + s_c;
    const __half* gB1 = B + (size_t)(n0 + s_row + 64) * K + s_c;
    const unsigned dA0 = (unsigned)__cvta_generic_to_shared(&sh [swz(s_row,      s_c)]);
    const unsigned dA1 = (unsigned)__cvta_generic_to_shared(&sh [swz(s_row + 64, s_c)]);
    const unsigned dB0 = (unsigned)__cvta_generic_to_shared(&shB[swz(s_row,      s_c)]);
    const unsigned dB1 = (unsigned)__cvta_generic_to_shared(&shB[swz(s_row + 64, s_c)]);

    auto stage = [&](int s) {
        unsigned o = (unsigned)((s & 3) * V3_TILE * 2);
        int kofs = s * 32;
        cp16(dA0 + o, gA0 + kofs);
        cp16(dA1 + o, gA1 + kofs);
        cp16(dB0 + o, gB0 + kofs);
        cp16(dB1 + o, gB1 + kofs);
        cp_commit();
    };

    stage(0); stage(1);

    for (int kt = 0; kt < nk; ++kt) {
        if (kt + 2 < nk) { stage(kt + 2); cp_wait<2>(); }
        else             { cp_wait<0>(); }
        __syncthreads();

        const __half* bA = sh  + (kt & 3) * V3_TILE;
        const __half* bB = shB + (kt & 3) * V3_TILE;
        #pragma unroll
        for (int ks = 0; ks < 32; ks += 16) {
            unsigned af[4][4];
            #pragma unroll
            for (int mf = 0; mf < 4; ++mf) {
                int row = wm * 64 + mf * 16 + (lane & 15);
                ldm_x4(af[mf][0], af[mf][1], af[mf][2], af[mf][3],
                       &bA[swz(row, ks + ((lane >> 4) << 3))]);
            }
            unsigned bf[4][2];
            #pragma unroll
            for (int nf2 = 0; nf2 < 2; ++nf2) {
                int g = lane >> 3;
                int row = wn * 32 + nf2 * 16 + ((g >> 1) << 3) + (lane & 7);
                unsigned t0, t1, t2, t3;
                ldm_x4(t0, t1, t2, t3, &bB[swz(row, ks + ((g & 1) << 3))]);
                bf[nf2*2][0] = t0; bf[nf2*2][1] = t1;
                bf[nf2*2+1][0] = t2; bf[nf2*2+1][1] = t3;
            }
            #pragma unroll
            for (int mf = 0; mf < 4; ++mf)
                #pragma unroll
                for (int nf = 0; nf < 4; ++nf)
                    mma_f16(acc[mf][nf], af[mf], bf[nf]);
        }
    }

    #pragma unroll
    for (int mf = 0; mf < 4; ++mf) {
        #pragma unroll
        for (int nf = 0; nf < 4; ++nf) {
            int row = m0 + wm * 64 + mf * 16 + (lane >> 2);
            int col = n0 + wn * 32 + nf * 8 + (lane & 3) * 2;
            float b0 = bias ? bias[col]     : 0.f;
            float b1 = bias ? bias[col + 1] : 0.f;
            #pragma unroll
            for (int half = 0; half < 2; ++half) {
                int r = row + half * 8;
                if (r >= Mreal) continue;
                float v0 = acc[mf][nf][half*2 + 0] + b0;
                float v1 = acc[mf][nf][half*2 + 1] + b1;
                size_t idx;
                if (REMAP) { int b_ = r & 63, t_ = r >> 6; idx = ((size_t)(b_ * TT + t_)) * N + col; }
                else       { idx = (size_t)r * N + col; }
                *(float2*)(C + idx) = make_float2(v0, v1);
            }
        }
    }
}

// ---------------------------------------------------------------- persistent GRU (64 CTAs x 16 cols)
// W_hh slice resident in smem (3 gates x 16 cols x 1024 = 96 KB); h staged via
// cp.async 3-buffer ring (48 KB); GH reduce 12 KB. One CTA per 16 hidden cols.
// Halves redundant h_prev L2 traffic vs the 128-CTA version (8 MB/step).
#define GRU_NCTA 64
#define GRU_SB_BYTES (3 * 16 * GG * 2)        // 98304
#define GRU_SA_BYTES (3 * 16384)              // 49152
#define GRU_GH_BYTES (3 * 64 * 16 * 4)        // 12288
#define GRU_SMEM (GRU_SB_BYTES + GRU_SA_BYTES + GRU_GH_BYTES)   // 159744

__global__ __launch_bounds__(384) void gru_persistent_kernel(
    const __half* __restrict__ Whh, const float* __restrict__ bhh) {
    extern __shared__ char gsm[];
    __half* sB  = (__half*)gsm;                          // 96 tiles of 16x32 (512 halfs)
    __half* sA  = (__half*)(gsm + GRU_SB_BYTES);         // 3 bufs x [q][64*32]
    float*  GHf = (float*)(gsm + GRU_SB_BYTES + GRU_SA_BYTES);  // [3][64][16]

    const int tid = threadIdx.x, lane = tid & 31, warp = tid >> 5;
    const int gate = warp % 3, kq = warp / 3;
    const int j0 = blockIdx.x * 16;

    // load W_hh slice once: 96 tiles x 16 rows x 4 chunks of 8 halfs = 6144 uint4
    for (int i = tid; i < 6144; i += 384) {
        int tile = i >> 6, rem = i & 63;
        int n = rem >> 2, c = (rem & 3) * 8;
        int kt = tile / 12, q = (tile / 3) & 3, g = tile % 3;
        *(uint4*)&sB[tile * 512 + swz(n, c)] =
            *(const uint4*)(Whh + (size_t)(g * GG + j0 + n) * GG + q * 256 + kt * 32 + c);
    }
    __syncthreads();

    for (int t = 0; t < TT; ++t) {
        const __half* hprev = (t == 0) ? nullptr : (d_HSh + (size_t)(t - 1) * BB * GG);
        const float*  hp32  = (t == 0) ? nullptr : (d_HS  + (size_t)(t - 1) * BB * GG);

        float acc[4][2][4];
        #pragma unroll
        for (int i = 0; i < 4; ++i)
            #pragma unroll
            for (int j = 0; j < 2; ++j)
                #pragma unroll
                for (int k = 0; k < 4; ++k) acc[i][j][k] = 0.f;

        if (t > 0) {
            auto stageA = [&](int kt) {
                __half* base = sA + (kt % 3) * 8192;
                for (int i = tid; i < 1024; i += 384) {
                    int q = i >> 8, rem = i & 255, row = rem >> 2, c = (rem & 3) * 8;
                    cp16((unsigned)__cvta_generic_to_shared(&base[q * 2048 + swz(row, c)]),
                         hprev + (size_t)row * GG + q * 256 + kt * 32 + c);
                }
                cp_commit();
            };
            stageA(0);
            for (int kt = 0; kt < 8; ++kt) {
                if (kt < 7) { stageA(kt + 1); cp_wait<1>(); }
                else        { cp_wait<0>(); }
                __syncthreads();
                const __half* bA = sA + (kt % 3) * 8192 + kq * 2048;
                const __half* bW = sB + ((kt * 4 + kq) * 3 + gate) * 512;
                #pragma unroll
                for (int ks = 0; ks < 32; ks += 16) {
                    unsigned af[4][4];
                    #pragma unroll
                    for (int mf = 0; mf < 4; ++mf) {
                        int row = mf * 16 + (lane & 15);
                        ldm_x4(af[mf][0], af[mf][1], af[mf][2], af[mf][3],
                               &bA[swz(row, ks + ((lane >> 4) << 3))]);
                    }
                    // B fragments: 16 n-rows x 16 k
                    unsigned bf[2][2];
                    {
                        int g2 = lane >> 3;
                        int row = ((g2 >> 1) << 3) + (lane & 7);
                        unsigned t0, t1, t2, t3;
                        ldm_x4(t0, t1, t2, t3, &bW[swz(row, ks + ((g2 & 1) << 3))]);
                        bf[0][0] = t0; bf[0][1] = t1;
                        bf[1][0] = t2; bf[1][1] = t3;
                    }
                    #pragma unroll
                    for (int mf = 0; mf < 4; ++mf) {
                        mma_f16(acc[mf][0], af[mf], bf[0]);
                        mma_f16(acc[mf][1], af[mf], bf[1]);
                    }
                }
            }
            __syncthreads();   // all mma done before GH reuse
        }

        // reduce 4 K-quarters into GH[gate][m][n], n in [0,16)
        for (int i = tid; i < 3 * 64 * 16; i += 384) GHf[i] = 0.f;
        __syncthreads();
        #pragma unroll 1
        for (int q = 0; q < 4; ++q) {
            if (kq == q) {
                #pragma unroll
                for (int mf = 0; mf < 4; ++mf)
                    #pragma unroll
                    for (int nf = 0; nf < 2; ++nf)
                        #pragma unroll
                        for (int ci = 0; ci < 4; ++ci) {
                            int m = mf * 16 + (lane >> 2) + ((ci >= 2) ? 8 : 0);
                            int n = nf * 8 + (lane & 3) * 2 + (ci & 1);
                            GHf[(gate * 64 + m) * 16 + n] += acc[mf][nf][ci];
                        }
            }
            __syncthreads();
        }

        // cell update: 64 x 16
        for (int idx = tid; idx < 64 * 16; idx += 384) {
            int m = idx >> 4, n = idx & 15;
            int j = j0 + n;
            float ghr = GHf[(0 * 64 + m) * 16 + n] + bhh[j];
            float ghz = GHf[(1 * 64 + m) * 16 + n] + bhh[GG + j];
            float ghn = GHf[(2 * 64 + m) * 16 + n] + bhh[2 * GG + j];
            const float* gi = d_GI + ((size_t)t * BB + m) * (3 * GG);
            float r  = sigmoidf_fast(gi[j]        + ghr);
            float z  = sigmoidf_fast(gi[GG + j]   + ghz);
            float nn = tanhf        (gi[2*GG + j] + r * ghn);
            float hp = hp32 ? hp32[(size_t)m * GG + j] : 0.f;
            float hn = (1.f - z) * nn + z * hp;
            d_HS [((size_t)t * BB + m) * GG + j] = hn;
            d_HSh[((size_t)t * BB + m) * GG + j] = __float2half_rn(hn);
        }

        // cross-CTA step barrier (skip after last step)
        if (t < TT - 1) {
            __threadfence();
            __syncthreads();
            if (tid == 0) {
                atomicAdd(&d_gru_bar, 1u);
                unsigned target = (unsigned)GRU_NCTA * (unsigned)(t + 1);
                while (*(volatile unsigned*)&d_gru_bar < target) { }
            }
            __syncthreads();
            __threadfence();
        }
    }
}

// ---------------------------------------------------------------- launch
extern "C" void kernel_launch(void* const* d_in, const int* in_sizes, int n_in,
                              void* d_out, int out_size) {
    const float* features = (const float*)d_in[0];
    const int*   input_ids= (const int*)  d_in[1];
    const float* emb      = (const float*)d_in[2];
    const float* img_v    = (const float*)d_in[3];
    const float* img_g    = (const float*)d_in[4];
    const float* img_b    = (const float*)d_in[5];
    const float* W_ih     = (const float*)d_in[6];
    const float* W_hh     = (const float*)d_in[7];
    const float* b_ih     = (const float*)d_in[8];
    const float* b_hh     = (const float*)d_in[9];
    const float* fc_v     = (const float*)d_in[10];
    const float* fc_g     = (const float*)d_in[11];
    const float* fc_b     = (const float*)d_in[12];
    float* out = (float*)d_out;

    float *dGI;  __half *dHSh, *dXh, *dFeat, *dWih, *dWhh, *dImgv, *dFcv;
    cudaGetSymbolAddress((void**)&dGI,  d_GI);
    cudaGetSymbolAddress((void**)&dHSh, d_HSh);
    cudaGetSymbolAddress((void**)&dXh,  d_Xh);
    cudaGetSymbolAddress((void**)&dFeat,d_feat_h);
    cudaGetSymbolAddress((void**)&dWih, d_Wih_h);
    cudaGetSymbolAddress((void**)&dWhh, d_Whh_h);
    cudaGetSymbolAddress((void**)&dImgv,d_imgv_h);
    cudaGetSymbolAddress((void**)&dFcv, d_fcv_h);

    cudaFuncSetAttribute(gemm_f16_v3<0>,
                         cudaFuncAttributeMaxDynamicSharedMemorySize, V3_SMEM);
    cudaFuncSetAttribute(gemm_f16_v3<1>,
                         cudaFuncAttributeMaxDynamicSharedMemorySize, V3_SMEM);
    cudaFuncSetAttribute(gru_persistent_kernel,
                         cudaFuncAttributeMaxDynamicSharedMemorySize, GRU_SMEM);

    static cudaStream_t s2 = nullptr;
    static cudaEvent_t ev_root = nullptr, ev_whh = nullptr, ev_fcv = nullptr;
    if (!s2) {
        int leastPri = 0, greatestPri = 0;
        cudaDeviceGetStreamPriorityRange(&leastPri, &greatestPri);
        cudaStreamCreateWithPriority(&s2, cudaStreamNonBlocking, leastPri);
        cudaEventCreateWithFlags(&ev_root, cudaEventDisableTiming);
        cudaEventCreateWithFlags(&ev_whh,  cudaEventDisableTiming);
        cudaEventCreateWithFlags(&ev_fcv,  cudaEventDisableTiming);
    }

    // fork side stream: W_hh f2h (quick, GRU dep) then fc_v weight-norm (FC dep)
    cudaEventRecord(ev_root, 0);
    cudaStreamWaitEvent(s2, ev_root, 0);
    f2h_kernel<<<(3*GG*GG/4 + 255)/256, 256, 0, s2>>>(W_hh, dWhh, 3*GG*GG);
    cudaEventRecord(ev_whh, s2);
    wn1024_kernel<<<(VV*32 + 255)/256, 256, 0, s2>>>(fc_v, fc_g, dFcv, VV);
    cudaEventRecord(ev_fcv, s2);

    // main stream: prep (feat/W_ih conv + img weight-norm + gather + bar reset)
    prep_kernel<<<PREP_BLOCKS, 256>>>(features, W_ih, img_v, img_g,
                                      input_ids, emb, dFeat, dWih, dImgv);

    // img embed GEMM (t=0 rows of X)
    {
        dim3 grid(1, EE / 128);
        gemm_f16_kernel<0,1><<<grid, 256>>>(dFeat, dImgv, dXh, img_b, BB, EE, FF);
    }

    // GI = X @ W_ih^T + b_ih   (M=1280, N=3072, K=512)
    {
        dim3 grid(MROWS / 128, (3 * GG) / 128);
        gemm_f16_v3<0><<<grid, 256, V3_SMEM>>>(dXh, dWih, dGI, b_ih, MROWS, 3 * GG, EE, 0);
    }

    // persistent GRU (64 CTAs, 20 internal steps) — needs Whh conversion done
    cudaStreamWaitEvent(0, ev_whh, 0);
    gru_persistent_kernel<<<GRU_NCTA, 384, GRU_SMEM>>>(dWhh, b_hh);

    // FC after join with fc_v conversion
    cudaStreamWaitEvent(0, ev_fcv, 0);
    {
        dim3 grid(MROWS / 128, VV / 128);
        gemm_f16_v3<1><<<grid, 256, V3_SMEM>>>(dHSh, dFcv, out, fc_b, MROWS, VV, GG, 0);
    }
    (void)in_sizes; (void)n_in; (void)out_size;
}

// round 15
// speedup vs baseline: 1.1884x; 1.1884x over previous
#include <cuda_runtime.h>
#include <cuda_fp16.h>
#include <math.h>
#include <stdint.h>

// Problem dims (fixed)
#define BB   64
#define TT   20
#define FF   2048
#define EE   512
#define GG   1024
#define VV   32000
#define MROWS (BB*TT)   // 1280

// Scratch (device globals; no allocation allowed)
__device__ float  d_GI [MROWS * 3 * GG];
__device__ float  d_HS [MROWS * GG];
__device__ __half d_HSh[MROWS * GG];
__device__ __half d_Xh [MROWS * EE];
__device__ __half d_feat_h[BB * FF];
__device__ __half d_Wih_h [3 * GG * EE];
__device__ __half d_Whh_h [3 * GG * GG];
__device__ __half d_imgv_h[EE * FF];
__device__ __half d_fcv_h [VV * GG];
__device__ float  d_imgpart[16 * BB * EE];   // split-K partials for img embed
__device__ unsigned d_gru_bar;               // global step barrier (reset in prep)

// ---------------------------------------------------------------- helpers
__device__ __forceinline__ void mma_f16(float c[4], const unsigned a[4], const unsigned b[2]) {
    asm volatile(
      "mma.sync.aligned.m16n8k16.row.col.f32.f16.f16.f32 "
      "{%0,%1,%2,%3},{%4,%5,%6,%7},{%8,%9},{%0,%1,%2,%3};\n"
      : "+f"(c[0]), "+f"(c[1]), "+f"(c[2]), "+f"(c[3])
      : "r"(a[0]), "r"(a[1]), "r"(a[2]), "r"(a[3]), "r"(b[0]), "r"(b[1]));
}
__device__ __forceinline__ void ldm_x4(unsigned& r0, unsigned& r1, unsigned& r2, unsigned& r3,
                                       const __half* p) {
    unsigned a = (unsigned)__cvta_generic_to_shared(p);
    asm volatile("ldmatrix.sync.aligned.m8n8.x4.shared.b16 {%0,%1,%2,%3}, [%4];"
                 : "=r"(r0), "=r"(r1), "=r"(r2), "=r"(r3) : "r"(a));
}
__device__ __forceinline__ void ldm_x2(unsigned& r0, unsigned& r1, const __half* p) {
    unsigned a = (unsigned)__cvta_generic_to_shared(p);
    asm volatile("ldmatrix.sync.aligned.m8n8.x2.shared.b16 {%0,%1}, [%2];"
                 : "=r"(r0), "=r"(r1) : "r"(a));
}
__device__ __forceinline__ void cp16(unsigned dst, const void* src) {
    asm volatile("cp.async.cg.shared.global [%0], [%1], 16;\n" :: "r"(dst), "l"(src));
}
__device__ __forceinline__ void cp_commit() {
    asm volatile("cp.async.commit_group;\n" ::: "memory");
}
template<int N> __device__ __forceinline__ void cp_wait() {
    asm volatile("cp.async.wait_group %0;\n" :: "n"(N) : "memory");
}
__device__ __forceinline__ float sigmoidf_fast(float x) {
    return 1.0f / (1.0f + __expf(-x));
}
__device__ __forceinline__ int swz(int row, int k) {
    int c = k >> 3;
    return ((row >> 1) << 6) + ((((((row & 1) << 2) | c)) ^ ((row >> 1) & 7)) << 3) + (k & 7);
}

// ---------------------------------------------------------------- merged prep
//   [0, 128)        : f2h features
//   [128, 1664)     : f2h W_ih
//   [1664, 4736)    : f2h W_hh
//   [4736, 4800)    : weight-norm img_v rows (warp per row, K=2048)
//   [4800, 5408)    : embedding gather (2 rows/block)
#define PREP_BLOCKS 5408

__global__ __launch_bounds__(256) void prep_kernel(
    const float* __restrict__ features,
    const float* __restrict__ W_ih,
    const float* __restrict__ W_hh,
    const float* __restrict__ img_v, const float* __restrict__ img_g,
    const int*   __restrict__ ids,   const float* __restrict__ emb,
    __half* __restrict__ feat_h, __half* __restrict__ Wih_h,
    __half* __restrict__ Whh_h,  __half* __restrict__ imgv_h) {
    const int bid = blockIdx.x, tid = threadIdx.x;
    if (bid == 0 && tid == 0) d_gru_bar = 0;

    if (bid < 1664) {
        const float* src; __half* dst; int base;
        if (bid < 128) { src = features; dst = feat_h; base = bid; }
        else           { src = W_ih;     dst = Wih_h;  base = bid - 128; }
        int i = (base * 256 + tid) * 4;
        float4 v = *(const float4*)(src + i);
        __half2* d = (__half2*)(dst + i);
        d[0] = __floats2half2_rn(v.x, v.y);
        d[1] = __floats2half2_rn(v.z, v.w);
    } else if (bid < 4736) {
        int i = ((bid - 1664) * 256 + tid) * 4;
        float4 v = *(const float4*)(W_hh + i);
        __half2* d = (__half2*)(Whh_h + i);
        d[0] = __floats2half2_rn(v.x, v.y);
        d[1] = __floats2half2_rn(v.z, v.w);
    } else if (bid < 4800) {
        int w = (bid - 4736) * 8 + (tid >> 5);
        int lane = tid & 31;
        const float4* v = (const float4*)(img_v + (size_t)w * FF);
        float s = 0.f;
        #pragma unroll
        for (int i = 0; i < 16; ++i) {
            float4 x = v[i * 32 + lane];
            s += x.x*x.x + x.y*x.y + x.z*x.z + x.w*x.w;
        }
        #pragma unroll
        for (int o = 16; o; o >>= 1) s += __shfl_xor_sync(0xffffffffu, s, o);
        float sc = img_g[w] / sqrtf(s);
        uint2* o2 = (uint2*)(imgv_h + (size_t)w * FF);
        #pragma unroll
        for (int i = 0; i < 16; ++i) {
            float4 x = v[i * 32 + lane];
            __half2 a = __floats2half2_rn(x.x * sc, x.y * sc);
            __half2 b = __floats2half2_rn(x.z * sc, x.w * sc);
            uint2 pk; pk.x = *(unsigned*)&a; pk.y = *(unsigned*)&b;
            o2[i * 32 + lane] = pk;
        }
    } else {
        int r = (bid - 4800) * 2 + (tid >> 7);
        int t = r / BB + 1, b = r % BB;
        int id = ids[b * TT + t];
        int i = tid & 127;
        const float4* src = (const float4*)(emb + (size_t)id * EE);
        __half2* dst = (__half2*)(d_Xh + ((size_t)t * BB + b) * EE);
        float4 v = src[i];
        dst[2*i]   = __floats2half2_rn(v.x, v.y);
        dst[2*i+1] = __floats2half2_rn(v.z, v.w);
    }
}

// weight-norm fold + convert, K=1024 (fc_v), warp per row, register-resident
__global__ __launch_bounds__(256) void wn1024_kernel(
    const float* __restrict__ V, const float* __restrict__ g, __half* __restrict__ out,
    int rows) {
    int w = (blockIdx.x * blockDim.x + threadIdx.x) >> 5;
    if (w >= rows) return;
    int lane = threadIdx.x & 31;
    const float4* v = (const float4*)(V + (size_t)w * 1024);
    float4 buf[8];
    float s = 0.f;
    #pragma unroll
    for (int i = 0; i < 8; ++i) {
        buf[i] = v[i * 32 + lane];
        s += buf[i].x*buf[i].x + buf[i].y*buf[i].y + buf[i].z*buf[i].z + buf[i].w*buf[i].w;
    }
    #pragma unroll
    for (int o = 16; o; o >>= 1) s += __shfl_xor_sync(0xffffffffu, s, o);
    float sc = g[w] / sqrtf(s);
    uint2* o2 = (uint2*)(out + (size_t)w * 1024);
    #pragma unroll
    for (int i = 0; i < 8; ++i) {
        __half2 a = __floats2half2_rn(buf[i].x * sc, buf[i].y * sc);
        __half2 b = __floats2half2_rn(buf[i].z * sc, buf[i].w * sc);
        uint2 pk; pk.x = *(unsigned*)&a; pk.y = *(unsigned*)&b;
        o2[i * 32 + lane] = pk;
    }
}

// ---------------------------------------------------------------- img embed: split-K GEMM
// features[64,2048] @ imgv^T[2048,512] -> partials [16][64][512] (fp32).
// Grid (16 kz, 4 n-tiles) = 64 CTAs, each 64x128 over a K=128 slice, one-shot smem.
#define IMG_SMEM ((8192 + 16384) * 2)     // A 16KB + B 32KB = 49152 bytes

__global__ __launch_bounds__(256) void img_splitk_kernel(
    const __half* __restrict__ A, const __half* __restrict__ B,
    float* __restrict__ part) {
    extern __shared__ __half ish[];
    __half* sA = ish;           // 4 subtiles x [64 rows x 32 k] swizzled
    __half* sB = ish + 8192;    // 4 subtiles x [128 rows x 32 k]

    const int tid = threadIdx.x, lane = tid & 31, warp = tid >> 5;
    const int wm = warp >> 2, wn = warp & 3;        // 2 x 4
    const int kz = blockIdx.x, n0 = blockIdx.y * 128;
    const int kbase = kz * 128;

    // stage A: 1024 chunks of 8 halfs
    for (int i = tid; i < 1024; i += 256) {
        int row = i >> 4, c = (i & 15) * 8;
        cp16((unsigned)__cvta_generic_to_shared(&sA[(c >> 5) * 2048 + swz(row, c & 31)]),
             A + (size_t)row * FF + kbase + c);
    }
    // stage B: 2048 chunks
    for (int i = tid; i < 2048; i += 256) {
        int row = i >> 4, c = (i & 15) * 8;
        cp16((unsigned)__cvta_generic_to_shared(&sB[(c >> 5) * 4096 + swz(row, c & 31)]),
             B + (size_t)(n0 + row) * FF + kbase + c);
    }
    cp_commit(); cp_wait<0>();
    __syncthreads();

    float acc[2][4][4];
    #pragma unroll
    for (int i = 0; i < 2; ++i)
        #pragma unroll
        for (int j = 0; j < 4; ++j)
            #pragma unroll
            for (int k = 0; k < 4; ++k) acc[i][j][k] = 0.f;

    #pragma unroll
    for (int kt = 0; kt < 4; ++kt) {
        const __half* bA = sA + kt * 2048;
        const __half* bB = sB + kt * 4096;
        #pragma unroll
        for (int ks = 0; ks < 32; ks += 16) {
            unsigned af[2][4];
            #pragma unroll
            for (int mf = 0; mf < 2; ++mf) {
                int row = wm * 32 + mf * 16 + (lane & 15);
                ldm_x4(af[mf][0], af[mf][1], af[mf][2], af[mf][3],
                       &bA[swz(row, ks + ((lane >> 4) << 3))]);
            }
            unsigned bf[4][2];
            #pragma unroll
            for (int nf2 = 0; nf2 < 2; ++nf2) {
                int g = lane >> 3;
                int row = wn * 32 + nf2 * 16 + ((g >> 1) << 3) + (lane & 7);
                unsigned t0, t1, t2, t3;
                ldm_x4(t0, t1, t2, t3, &bB[swz(row, ks + ((g & 1) << 3))]);
                bf[nf2*2][0] = t0; bf[nf2*2][1] = t1;
                bf[nf2*2+1][0] = t2; bf[nf2*2+1][1] = t3;
            }
            #pragma unroll
            for (int mf = 0; mf < 2; ++mf)
                #pragma unroll
                for (int nf = 0; nf < 4; ++nf)
                    mma_f16(acc[mf][nf], af[mf], bf[nf]);
        }
    }

    float* po = part + (size_t)kz * (BB * EE);
    #pragma unroll
    for (int mf = 0; mf < 2; ++mf) {
        #pragma unroll
        for (int nf = 0; nf < 4; ++nf) {
            int row = wm * 32 + mf * 16 + (lane >> 2);
            int col = n0 + wn * 32 + nf * 8 + (lane & 3) * 2;
            #pragma unroll
            for (int half = 0; half < 2; ++half) {
                int r = row + half * 8;
                *(float2*)(po + (size_t)r * EE + col) =
                    make_float2(acc[mf][nf][half*2], acc[mf][nf][half*2 + 1]);
            }
        }
    }
}

// reduce 16 split-K partials + bias -> fp16 X rows for t=0
__global__ __launch_bounds__(128) void img_reduce_kernel(
    const float* __restrict__ part, const float* __restrict__ bias) {
    int i = (blockIdx.x * 128 + threadIdx.x) * 4;    // 0..32767, grid 64
    float4 s = make_float4(0.f, 0.f, 0.f, 0.f);
    #pragma unroll
    for (int kz = 0; kz < 16; ++kz) {
        float4 v = *(const float4*)(part + (size_t)kz * (BB * EE) + i);
        s.x += v.x; s.y += v.y; s.z += v.z; s.w += v.w;
    }
    int e = i & (EE - 1);
    float4 bv = *(const float4*)(bias + e);
    __half2* dst = (__half2*)(d_Xh + i);             // t=0 rows: Xh[b*EE + e]
    dst[0] = __floats2half2_rn(s.x + bv.x, s.y + bv.y);
    dst[1] = __floats2half2_rn(s.z + bv.z, s.w + bv.w);
}

// ---------------------------------------------------------------- mma.sync GEMM v3 (FC, GI)
// 256 threads (8 warps 2x4), BM=BN=128, BK=32, 4-stage cp.async ring,
// stage-before-barrier, ONE __syncthreads per k-tile, depth-2 prefetch, 2 CTAs/SM.
#define V3_TILE 4096
#define V3_SMEM (8 * V3_TILE * 2)          // 64 KB

template<int REMAP>
__global__ __launch_bounds__(256, 2) void gemm_f16_v3(
    const __half* __restrict__ A, const __half* __restrict__ B, float* __restrict__ C,
    const float* __restrict__ bias, int Mreal, int N, int K, int m_ofs) {
    extern __shared__ __half sh[];
    __half* shB = sh + 4 * V3_TILE;

    const int tid = threadIdx.x, lane = tid & 31, warp = tid >> 5;
    const int wm = warp >> 2, wn = warp & 3;
    const int m0 = m_ofs + blockIdx.x * 128, n0 = blockIdx.y * 128;

    float acc[4][4][4];
    #pragma unroll
    for (int i = 0; i < 4; ++i)
        #pragma unroll
        for (int j = 0; j < 4; ++j)
            #pragma unroll
            for (int k = 0; k < 4; ++k) acc[i][j][k] = 0.f;

    const int nk = K >> 5;

    const int s_row = tid >> 2, s_c = (tid & 3) * 8;
    int ar0 = m0 + s_row;      if (ar0 >= Mreal) ar0 = Mreal - 1;
    int ar1 = m0 + s_row + 64; if (ar1 >= Mreal) ar1 = Mreal - 1;
    const __half* gA0 = A + (size_t)ar0 * K + s_c;
    const __half* gA1 = A + (size_t)ar1 * K + s_c;
    const __half* gB0 = B + (size_t)(n0 + s_row)      * K + s_c;
    const __half* gB1 = B + (size_t)(n0 + s_row + 64) * K + s_c;
    const unsigned dA0 = (unsigned)__cvta_generic_to_shared(&sh [swz(s_row,      s_c)]);
    const unsigned dA1 = (unsigned)__cvta_generic_to_shared(&sh [swz(s_row + 64, s_c)]);
    const unsigned dB0 = (unsigned)__cvta_generic_to_shared(&shB[swz(s_row,      s_c)]);
    const unsigned dB1 = (unsigned)__cvta_generic_to_shared(&shB[swz(s_row + 64, s_c)]);

    auto stage = [&](int s) {
        unsigned o = (unsigned)((s & 3) * V3_TILE * 2);
        int kofs = s * 32;
        cp16(dA0 + o, gA0 + kofs);
        cp16(dA1 + o, gA1 + kofs);
        cp16(dB0 + o, gB0 + kofs);
        cp16(dB1 + o, gB1 + kofs);
        cp_commit();
    };

    stage(0); stage(1);

    for (int kt = 0; kt < nk; ++kt) {
        if (kt + 2 < nk) { stage(kt + 2); cp_wait<2>(); }
        else             { cp_wait<0>(); }
        __syncthreads();

        const __half* bA = sh  + (kt & 3) * V3_TILE;
        const __half* bB = shB + (kt & 3) * V3_TILE;
        #pragma unroll
        for (int ks = 0; ks < 32; ks += 16) {
            unsigned af[4][4];
            #pragma unroll
            for (int mf = 0; mf < 4; ++mf) {
                int row = wm * 64 + mf * 16 + (lane & 15);
                ldm_x4(af[mf][0], af[mf][1], af[mf][2], af[mf][3],
                       &bA[swz(row, ks + ((lane >> 4) << 3))]);
            }
            unsigned bf[4][2];
            #pragma unroll
            for (int nf2 = 0; nf2 < 2; ++nf2) {
                int g = lane >> 3;
                int row = wn * 32 + nf2 * 16 + ((g >> 1) << 3) + (lane & 7);
                unsigned t0, t1, t2, t3;
                ldm_x4(t0, t1, t2, t3, &bB[swz(row, ks + ((g & 1) << 3))]);
                bf[nf2*2][0] = t0; bf[nf2*2][1] = t1;
                bf[nf2*2+1][0] = t2; bf[nf2*2+1][1] = t3;
            }
            #pragma unroll
            for (int mf = 0; mf < 4; ++mf)
                #pragma unroll
                for (int nf = 0; nf < 4; ++nf)
                    mma_f16(acc[mf][nf], af[mf], bf[nf]);
        }
    }

    #pragma unroll
    for (int mf = 0; mf < 4; ++mf) {
        #pragma unroll
        for (int nf = 0; nf < 4; ++nf) {
            int row = m0 + wm * 64 + mf * 16 + (lane >> 2);
            int col = n0 + wn * 32 + nf * 8 + (lane & 3) * 2;
            float b0 = bias ? bias[col]     : 0.f;
            float b1 = bias ? bias[col + 1] : 0.f;
            #pragma unroll
            for (int half = 0; half < 2; ++half) {
                int r = row + half * 8;
                if (r >= Mreal) continue;
                float v0 = acc[mf][nf][half*2 + 0] + b0;
                float v1 = acc[mf][nf][half*2 + 1] + b1;
                size_t idx;
                if (REMAP) { int b_ = r & 63, t_ = r >> 6; idx = ((size_t)(b_ * TT + t_)) * N + col; }
                else       { idx = (size_t)r * N + col; }
                *(float2*)(C + idx) = make_float2(v0, v1);
            }
        }
    }
}

// ---------------------------------------------------------------- persistent GRU (128 CTAs x 8 cols)
#define GRU_SMEM (49152 + 3*16384 + 6144)

__global__ __launch_bounds__(384) void gru_persistent_kernel(
    const __half* __restrict__ Whh, const float* __restrict__ bhh) {
    extern __shared__ char gsm[];
    __half* sB  = (__half*)gsm;
    __half* sA  = (__half*)(gsm + 49152);
    float*  GHf = (float*)(gsm + 49152 + 3*16384);

    const int tid = threadIdx.x, lane = tid & 31, warp = tid >> 5;
    const int gate = warp % 3, kq = warp / 3;
    const int j0 = blockIdx.x * 8;

    for (int i = tid; i < 3072; i += 384) {
        int tile = i >> 5, rem = i & 31;
        int n = rem >> 2, c = (rem & 3) * 8;
        int kt = tile / 12, q = (tile / 3) & 3, g = tile % 3;
        *(uint4*)&sB[tile * 256 + swz(n, c)] =
            *(const uint4*)(Whh + (size_t)(g * GG + j0 + n) * GG + q * 256 + kt * 32 + c);
    }
    __syncthreads();

    for (int t = 0; t < TT; ++t) {
        const __half* hprev = (t == 0) ? nullptr : (d_HSh + (size_t)(t - 1) * BB * GG);
        const float*  hp32  = (t == 0) ? nullptr : (d_HS  + (size_t)(t - 1) * BB * GG);

        float acc[4][4];
        #pragma unroll
        for (int i = 0; i < 4; ++i)
            #pragma unroll
            for (int j = 0; j < 4; ++j) acc[i][j] = 0.f;

        if (t > 0) {
            auto stageA = [&](int kt) {
                __half* base = sA + (kt % 3) * 8192;
                for (int i = tid; i < 1024; i += 384) {
                    int q = i >> 8, rem = i & 255, row = rem >> 2, c = (rem & 3) * 8;
                    cp16((unsigned)__cvta_generic_to_shared(&base[q * 2048 + swz(row, c)]),
                         hprev + (size_t)row * GG + q * 256 + kt * 32 + c);
                }
                cp_commit();
            };
            stageA(0);
            for (int kt = 0; kt < 8; ++kt) {
                if (kt < 7) { stageA(kt + 1); cp_wait<1>(); }
                else        { cp_wait<0>(); }
                __syncthreads();
                const __half* bA = sA + (kt % 3) * 8192 + kq * 2048;
                const __half* bW = sB + ((kt * 4 + kq) * 3 + gate) * 256;
                #pragma unroll
                for (int ks = 0; ks < 32; ks += 16) {
                    unsigned af[4][4];
                    #pragma unroll
                    for (int mf = 0; mf < 4; ++mf) {
                        int row = mf * 16 + (lane & 15);
                        ldm_x4(af[mf][0], af[mf][1], af[mf][2], af[mf][3],
                               &bA[swz(row, ks + ((lane >> 4) << 3))]);
                    }
                    unsigned bf[2];
                    ldm_x2(bf[0], bf[1], &bW[swz(lane & 7, ks + (lane & 8))]);
                    #pragma unroll
                    for (int mf = 0; mf < 4; ++mf) mma_f16(acc[mf], af[mf], bf);
                }
            }
            __syncthreads();
        }

        for (int i = tid; i < 3 * 64 * 8; i += 384) GHf[i] = 0.f;
        __syncthreads();
        #pragma unroll 1
        for (int q = 0; q < 4; ++q) {
            if (kq == q) {
                #pragma unroll
                for (int mf = 0; mf < 4; ++mf)
                    #pragma unroll
                    for (int ci = 0; ci < 4; ++ci) {
                        int m = mf * 16 + (lane >> 2) + ((ci >= 2) ? 8 : 0);
                        int n = (lane & 3) * 2 + (ci & 1);
                        GHf[(gate * 64 + m) * 8 + n] += acc[mf][ci];
                    }
            }
            __syncthreads();
        }

        for (int idx = tid; idx < 64 * 8; idx += 384) {
            int m = idx >> 3, n = idx & 7;
            int j = j0 + n;
            float ghr = GHf[(0 * 64 + m) * 8 + n] + bhh[j];
            float ghz = GHf[(1 * 64 + m) * 8 + n] + bhh[GG + j];
            float ghn = GHf[(2 * 64 + m) * 8 + n] + bhh[2 * GG + j];
            const float* gi = d_GI + ((size_t)t * BB + m) * (3 * GG);
            float r  = sigmoidf_fast(gi[j]        + ghr);
            float z  = sigmoidf_fast(gi[GG + j]   + ghz);
            float nn = tanhf        (gi[2*GG + j] + r * ghn);
            float hp = hp32 ? hp32[(size_t)m * GG + j] : 0.f;
            float hn = (1.f - z) * nn + z * hp;
            d_HS [((size_t)t * BB + m) * GG + j] = hn;
            d_HSh[((size_t)t * BB + m) * GG + j] = __float2half_rn(hn);
        }

        if (t < TT - 1) {
            __threadfence();
            __syncthreads();
            if (tid == 0) {
                atomicAdd(&d_gru_bar, 1u);
                unsigned target = 128u * (unsigned)(t + 1);
                while (*(volatile unsigned*)&d_gru_bar < target) { }
            }
            __syncthreads();
            __threadfence();
        }
    }
}

// ---------------------------------------------------------------- launch
extern "C" void kernel_launch(void* const* d_in, const int* in_sizes, int n_in,
                              void* d_out, int out_size) {
    const float* features = (const float*)d_in[0];
    const int*   input_ids= (const int*)  d_in[1];
    const float* emb      = (const float*)d_in[2];
    const float* img_v    = (const float*)d_in[3];
    const float* img_g    = (const float*)d_in[4];
    const float* img_b    = (const float*)d_in[5];
    const float* W_ih     = (const float*)d_in[6];
    const float* W_hh     = (const float*)d_in[7];
    const float* b_ih     = (const float*)d_in[8];
    const float* b_hh     = (const float*)d_in[9];
    const float* fc_v     = (const float*)d_in[10];
    const float* fc_g     = (const float*)d_in[11];
    const float* fc_b     = (const float*)d_in[12];
    float* out = (float*)d_out;

    float *dGI, *dPart;  __half *dHSh, *dXh, *dFeat, *dWih, *dWhh, *dImgv, *dFcv;
    cudaGetSymbolAddress((void**)&dGI,  d_GI);
    cudaGetSymbolAddress((void**)&dPart,d_imgpart);
    cudaGetSymbolAddress((void**)&dHSh, d_HSh);
    cudaGetSymbolAddress((void**)&dXh,  d_Xh);
    cudaGetSymbolAddress((void**)&dFeat,d_feat_h);
    cudaGetSymbolAddress((void**)&dWih, d_Wih_h);
    cudaGetSymbolAddress((void**)&dWhh, d_Whh_h);
    cudaGetSymbolAddress((void**)&dImgv,d_imgv_h);
    cudaGetSymbolAddress((void**)&dFcv, d_fcv_h);

    cudaFuncSetAttribute(gemm_f16_v3<0>,
                         cudaFuncAttributeMaxDynamicSharedMemorySize, V3_SMEM);
    cudaFuncSetAttribute(gemm_f16_v3<1>,
                         cudaFuncAttributeMaxDynamicSharedMemorySize, V3_SMEM);
    cudaFuncSetAttribute(img_splitk_kernel,
                         cudaFuncAttributeMaxDynamicSharedMemorySize, IMG_SMEM);
    cudaFuncSetAttribute(gru_persistent_kernel,
                         cudaFuncAttributeMaxDynamicSharedMemorySize, GRU_SMEM);

    static cudaStream_t s2 = nullptr;
    static cudaEvent_t ev_root = nullptr, ev_fcv = nullptr;
    if (!s2) {
        int leastPri = 0, greatestPri = 0;
        cudaDeviceGetStreamPriorityRange(&leastPri, &greatestPri);
        cudaStreamCreateWithPriority(&s2, cudaStreamNonBlocking, leastPri);
        cudaEventCreateWithFlags(&ev_root, cudaEventDisableTiming);
        cudaEventCreateWithFlags(&ev_fcv,  cudaEventDisableTiming);
    }

    // fork: fc_v weight-norm conversion on side stream
    cudaEventRecord(ev_root, 0);
    cudaStreamWaitEvent(s2, ev_root, 0);
    wn1024_kernel<<<(VV*32 + 255)/256, 256, 0, s2>>>(fc_v, fc_g, dFcv, VV);
    cudaEventRecord(ev_fcv, s2);

    // main: all prep (conversions + img weight-norm + gather + bar reset)
    prep_kernel<<<PREP_BLOCKS, 256>>>(features, W_ih, W_hh, img_v, img_g,
                                      input_ids, emb, dFeat, dWih, dWhh, dImgv);

    // img embed split-K (64 CTAs) + reduce -> Xh t=0 rows
    {
        dim3 grid(16, EE / 128);
        img_splitk_kernel<<<grid, 256, IMG_SMEM>>>(dFeat, dImgv, dPart);
        img_reduce_kernel<<<(BB * EE / 4) / 128, 128>>>(dPart, img_b);
    }

    // GI = X @ W_ih^T + b_ih   (M=1280, N=3072, K=512)
    {
        dim3 grid(MROWS / 128, (3 * GG) / 128);
        gemm_f16_v3<0><<<grid, 256, V3_SMEM>>>(dXh, dWih, dGI, b_ih, MROWS, 3 * GG, EE, 0);
    }

    // persistent GRU (128 CTAs, 20 internal steps)
    gru_persistent_kernel<<<128, 384, GRU_SMEM>>>(dWhh, b_hh);

    // FC after join with fc_v conversion
    cudaStreamWaitEvent(0, ev_fcv, 0);
    {
        dim3 grid(MROWS / 128, VV / 128);
        gemm_f16_v3<1><<<grid, 256, V3_SMEM>>>(dHSh, dFcv, out, fc_b, MROWS, VV, GG, 0);
    }
    (void)in_sizes; (void)n_in; (void)out_size;
}